// round 14
// baseline (speedup 1.0000x reference)
#include <cuda_runtime.h>
#include <cuda_fp16.h>
#include <cstdint>

#define N_USERS 100000
#define M_ITEMS 50000
#define N_NODES (N_USERS + M_ITEMS)        // 150000
#define N_EDGES 6000000
#define DIM 64
#define ROW_H2 (DIM / 2)                   // 32 half2 per node row
#define ROW_U2 (DIM / 4)                   // 16 uint2 (4 halfs) per node row
#define N_H2 ((size_t)N_NODES * ROW_H2)    // 4,800,000 half2

#define SCAN_B 1024
#define NB_SCAN ((N_NODES + SCAN_B - 1) / SCAN_B)   // 147

// ---- static scratch (no allocation allowed; zero-initialized at load) ------
__device__ __half2 g_b0[N_H2];       // 19.2 MB  h after 0 hops (quantized input)
__device__ __half2 g_b1[N_H2];       // 19.2 MB  h after 1 hop
__device__ __half2 g_b2[N_H2];       // 19.2 MB  h after 2 hops
__device__ int2    g_edges[N_EDGES]; // 48 MB    (src*ROW_U2, val_bits) sorted by dst
__device__ int     g_rank[N_EDGES];  // 24 MB    per-edge rank within its dst segment
__device__ int     g_cnt[N_NODES];   // INVARIANT: == 0 at kernel_launch entry
                                     // (zeroed by final spmm of previous run;
                                     //  zero-init on first run)
__device__ int     g_off[N_NODES];

// ---------------------------------------------------------------------------
// Fused: b0 = fp16(concat(user_emb, item_emb))  AND  histogram of dst with
// rank capture (2 edges per thread). atomicAdd-with-return costs the same L2
// throughput as REDG at this contention level; the rank store is coalesced.
// Requires g_cnt == 0 at entry (see invariant above).
// ---------------------------------------------------------------------------
__global__ void init_hist_kernel(const float* __restrict__ user_emb,
                                 const float* __restrict__ item_emb,
                                 const int*   __restrict__ dst) {
    size_t i = (size_t)blockIdx.x * blockDim.x + threadIdx.x;
    if (i < N_H2) {
        size_t user2 = (size_t)N_USERS * ROW_H2;
        float2 v = (i < user2) ? ((const float2*)user_emb)[i]
                               : ((const float2*)item_emb)[i - user2];
        g_b0[i] = __floats2half2_rn(v.x, v.y);
    }
    if (i < N_EDGES / 2) {
        int2 d = __ldg((const int2*)dst + i);
        int r0 = atomicAdd(&g_cnt[d.x], 1);
        int r1 = atomicAdd(&g_cnt[d.y], 1);
        ((int2*)g_rank)[i] = make_int2(r0, r1);
    }
}

// ---------------------------------------------------------------------------
// Exclusive scan of g_cnt -> g_off (single kernel).
// Block b computes its base by directly summing g_cnt[0 .. b*SCAN_B).
// ---------------------------------------------------------------------------
__global__ void scan_kernel() {
    __shared__ int sm[SCAN_B];
    int b = blockIdx.x;

    int acc = 0;
    int lim = b * SCAN_B;
    if (lim > N_NODES) lim = N_NODES;
    for (int k = threadIdx.x; k < lim; k += SCAN_B) acc += g_cnt[k];
    sm[threadIdx.x] = acc;
    __syncthreads();
    for (int s = SCAN_B / 2; s > 0; s >>= 1) {
        if (threadIdx.x < s) sm[threadIdx.x] += sm[threadIdx.x + s];
        __syncthreads();
    }
    int base = sm[0];
    __syncthreads();

    int idx = b * SCAN_B + threadIdx.x;
    int x = (idx < N_NODES) ? g_cnt[idx] : 0;
    sm[threadIdx.x] = x;
    __syncthreads();
    for (int o = 1; o < SCAN_B; o <<= 1) {
        int t = (threadIdx.x >= o) ? sm[threadIdx.x - o] : 0;
        __syncthreads();
        sm[threadIdx.x] += t;
        __syncthreads();
    }
    if (idx < N_NODES) {
        int excl = sm[threadIdx.x] - x + base;
        g_off[idx] = excl;
    }
}

// ---------------------------------------------------------------------------
// Counting-sort placement WITHOUT atomics (2 edges per thread):
// pos = g_off[dst] + precomputed rank. g_off is 600KB (L2-resident, ~40x
// reuse). record = (src * ROW_U2, f32 val bits).
// ---------------------------------------------------------------------------
__global__ void scatter_kernel(const int* __restrict__ src,
                               const int* __restrict__ dst,
                               const float* __restrict__ val) {
    int e = blockIdx.x * blockDim.x + threadIdx.x;
    if (e < N_EDGES / 2) {
        int2   s = __ldg((const int2*)src + e);
        int2   d = __ldg((const int2*)dst + e);
        float2 v = __ldg((const float2*)val + e);
        int2   r = ((const int2*)g_rank)[e];
        int p0 = __ldg(&g_off[d.x]) + r.x;
        int p1 = __ldg(&g_off[d.y]) + r.y;
        g_edges[p0] = make_int2(s.x * ROW_U2, __float_as_int(v.x));
        g_edges[p1] = make_int2(s.y * ROW_U2, __float_as_int(v.y));
    }
}

// ---------------------------------------------------------------------------
// CSR SpMM, pair scheme (R7-proven: 32 regs, 84% occ, 77.2-77.9us measured
// three times): one warp per destination node; lanes 0-15 process even
// edges, lanes 16-31 odd edges; each lane owns 4 dims (uint2 = 2 half2).
// Per inner iteration 2 edges: 1 LDS.64 + 1 LDG.64 + 4 cvt + 4 FFMA / lane.
// f32 accumulation, cross-half combine via SHFL.XOR(16).
// FINAL fuses out = (b0+b1+b2+h3)*0.25 and restores g_cnt == 0.
// ---------------------------------------------------------------------------
template<bool FINAL>
__global__ __launch_bounds__(256)
void spmm_csr_kernel(const __half2* __restrict__ hin,
                     __half2* __restrict__ hout,
                     float* __restrict__ out) {
    __shared__ int2 sm_ed[8][32];
    int wl   = threadIdx.x >> 5;
    int node = blockIdx.x * (blockDim.x >> 5) + wl;
    int lane = threadIdx.x & 31;
    if (node >= N_NODES) return;

    int start = g_off[node];
    int n     = g_cnt[node];
    int half  = lane >> 4;       // which edge of the pair this lane serves
    int hoff  = lane & 15;       // which uint2 (4 dims) of the row

    const uint2* __restrict__ hp = (const uint2*)hin;

    float s0 = 0.f, s1 = 0.f, s2 = 0.f, s3 = 0.f;
    int i = 0;
    for (; i + 32 <= n; i += 32) {
        sm_ed[wl][lane] = __ldg(&g_edges[start + i + lane]);
        __syncwarp();
        #pragma unroll
        for (int j = 0; j < 16; j++) {
            int2 e  = sm_ed[wl][2 * j + half];
            float v = __int_as_float(e.y);
            uint2 x = __ldg(&hp[e.x + hoff]);
            float2 fa = __half22float2(*(const __half2*)&x.x);
            float2 fb = __half22float2(*(const __half2*)&x.y);
            s0 += v * fa.x; s1 += v * fa.y;
            s2 += v * fb.x; s3 += v * fb.y;
        }
        __syncwarp();
    }
    int rem = n - i;
    if (rem > 0) {
        int2 ed = make_int2(0, 0);                      // zero-pad (v=0)
        if (lane < rem) ed = __ldg(&g_edges[start + i + lane]);
        sm_ed[wl][lane] = ed;
        __syncwarp();
        int npair = (rem + 1) >> 1;
        for (int j = 0; j < npair; j++) {
            int2 e  = sm_ed[wl][2 * j + half];
            float v = __int_as_float(e.y);
            uint2 x = __ldg(&hp[e.x + hoff]);
            float2 fa = __half22float2(*(const __half2*)&x.x);
            float2 fb = __half22float2(*(const __half2*)&x.y);
            s0 += v * fa.x; s1 += v * fa.y;
            s2 += v * fb.x; s3 += v * fb.y;
        }
    }

    // combine the two half-warps (even-edge sums + odd-edge sums)
    s0 += __shfl_xor_sync(0xffffffffu, s0, 16);
    s1 += __shfl_xor_sync(0xffffffffu, s1, 16);
    s2 += __shfl_xor_sync(0xffffffffu, s2, 16);
    s3 += __shfl_xor_sync(0xffffffffu, s3, 16);

    if (lane < 16) {
        size_t o = (size_t)node * ROW_U2 + hoff;        // uint2 / float4 index
        if (!FINAL) {
            __half2 ha = __floats2half2_rn(s0, s1);
            __half2 hb = __floats2half2_rn(s2, s3);
            uint2 r;
            r.x = *(const unsigned int*)&ha;
            r.y = *(const unsigned int*)&hb;
            ((uint2*)hout)[o] = r;
        } else {
            uint2 p0 = ((const uint2*)g_b0)[o];
            uint2 p1 = ((const uint2*)g_b1)[o];
            uint2 p2 = ((const uint2*)hin)[o];          // hin == g_b2 here
            float2 a0 = __half22float2(*(const __half2*)&p0.x);
            float2 b0_ = __half22float2(*(const __half2*)&p0.y);
            float2 a1 = __half22float2(*(const __half2*)&p1.x);
            float2 b1_ = __half22float2(*(const __half2*)&p1.y);
            float2 a2 = __half22float2(*(const __half2*)&p2.x);
            float2 b2_ = __half22float2(*(const __half2*)&p2.y);
            float4 r;
            r.x = (a0.x + a1.x + a2.x + s0) * 0.25f;
            r.y = (a0.y + a1.y + a2.y + s1) * 0.25f;
            r.z = (b0_.x + b1_.x + b2_.x + s2) * 0.25f;
            r.w = (b0_.y + b1_.y + b2_.y + s3) * 0.25f;
            ((float4*)out)[o] = r;
        }
    }
    if (FINAL && lane == 0) g_cnt[node] = 0;            // restore invariant
}

// ---------------------------------------------------------------------------
extern "C" void kernel_launch(void* const* d_in, const int* in_sizes, int n_in,
                              void* d_out, int out_size) {
    const float* user_emb = (const float*)d_in[0];
    const float* item_emb = (const float*)d_in[1];
    const int*   edge_src = (const int*)d_in[2];
    const int*   edge_dst = (const int*)d_in[3];
    const float* edge_val = (const float*)d_in[4];
    float* out = (float*)d_out;

    __half2 *b0, *b1, *b2;
    cudaGetSymbolAddress((void**)&b0, g_b0);
    cudaGetSymbolAddress((void**)&b1, g_b1);
    cudaGetSymbolAddress((void**)&b2, g_b2);

    const int TB = 256;
    const int grid_init  = (int)((N_H2 + TB - 1) / TB);            // covers 3M edge-pairs too
    const int grid_edge2 = (N_EDGES / 2 + TB - 1) / TB;
    const int grid_spmm  = (N_NODES * 32 + TB - 1) / TB;           // 1 warp / node

    // 0: fused init + dst histogram with rank capture
    init_hist_kernel<<<grid_init, TB>>>(user_emb, item_emb, edge_dst);
    // 1: exclusive scan -> g_off
    scan_kernel<<<NB_SCAN, SCAN_B>>>();
    // 2: atomic-free counting-sort placement (pos = off[dst] + rank)
    scatter_kernel<<<grid_edge2, TB>>>(edge_src, edge_dst, edge_val);

    // 3: Layer 1: b0 -> b1
    spmm_csr_kernel<false><<<grid_spmm, TB>>>(b0, b1, nullptr);
    // 4: Layer 2: b1 -> b2
    spmm_csr_kernel<false><<<grid_spmm, TB>>>(b1, b2, nullptr);
    // 5: Layer 3: b2 -> (h3 on the fly), out = (b0+b1+b2+h3) * 0.25, reset g_cnt
    spmm_csr_kernel<true><<<grid_spmm, TB>>>(b2, nullptr, out);
}

// round 15
// speedup vs baseline: 1.0593x; 1.0593x over previous
#include <cuda_runtime.h>
#include <cuda_fp16.h>
#include <cstdint>

#define N_USERS 100000
#define M_ITEMS 50000
#define N_NODES (N_USERS + M_ITEMS)        // 150000
#define N_EDGES 6000000
#define DIM 64
#define ROW_H2 (DIM / 2)                   // 32 half2 per node row
#define ROW_U2 (DIM / 4)                   // 16 uint2 (4 halfs) per node row
#define N_H2 ((size_t)N_NODES * ROW_H2)    // 4,800,000 half2

#define SCAN_B 1024
#define NB_SCAN ((N_NODES + SCAN_B - 1) / SCAN_B)   // 147

// ---- static scratch (no allocation allowed; zero-initialized at load) ------
__device__ __half2 g_b0[N_H2];       // 19.2 MB  h after 0 hops (quantized input)
__device__ __half2 g_b1[N_H2];       // 19.2 MB  h after 1 hop
__device__ __half2 g_b2[N_H2];       // 19.2 MB  h after 2 hops
__device__ int2    g_edges[N_EDGES]; // 48 MB    (src*ROW_U2, val_bits) sorted by dst
__device__ int     g_cnt[N_NODES];   // INVARIANT: == 0 at kernel_launch entry
                                     // (zeroed by final spmm of previous run;
                                     //  zero-init on first run)
__device__ int     g_off[N_NODES];
__device__ int     g_pos[N_NODES];

// ---------------------------------------------------------------------------
// Fused: b0 = fp16(concat(user_emb, item_emb))  AND  histogram of dst
// (2 edges per thread). Requires g_cnt == 0 at entry (see invariant above).
// ---------------------------------------------------------------------------
__global__ void init_hist_kernel(const float* __restrict__ user_emb,
                                 const float* __restrict__ item_emb,
                                 const int*   __restrict__ dst) {
    size_t i = (size_t)blockIdx.x * blockDim.x + threadIdx.x;
    if (i < N_H2) {
        size_t user2 = (size_t)N_USERS * ROW_H2;
        float2 v = (i < user2) ? ((const float2*)user_emb)[i]
                               : ((const float2*)item_emb)[i - user2];
        g_b0[i] = __floats2half2_rn(v.x, v.y);
    }
    if (i < N_EDGES / 2) {
        int2 d = __ldg((const int2*)dst + i);
        atomicAdd(&g_cnt[d.x], 1);
        atomicAdd(&g_cnt[d.y], 1);
    }
}

// ---------------------------------------------------------------------------
// Exclusive scan of g_cnt -> g_off, g_pos (single kernel).
// Block b computes its base by directly summing g_cnt[0 .. b*SCAN_B).
// ---------------------------------------------------------------------------
__global__ void scan_kernel() {
    __shared__ int sm[SCAN_B];
    int b = blockIdx.x;

    int acc = 0;
    int lim = b * SCAN_B;
    if (lim > N_NODES) lim = N_NODES;
    for (int k = threadIdx.x; k < lim; k += SCAN_B) acc += g_cnt[k];
    sm[threadIdx.x] = acc;
    __syncthreads();
    for (int s = SCAN_B / 2; s > 0; s >>= 1) {
        if (threadIdx.x < s) sm[threadIdx.x] += sm[threadIdx.x + s];
        __syncthreads();
    }
    int base = sm[0];
    __syncthreads();

    int idx = b * SCAN_B + threadIdx.x;
    int x = (idx < N_NODES) ? g_cnt[idx] : 0;
    sm[threadIdx.x] = x;
    __syncthreads();
    for (int o = 1; o < SCAN_B; o <<= 1) {
        int t = (threadIdx.x >= o) ? sm[threadIdx.x - o] : 0;
        __syncthreads();
        sm[threadIdx.x] += t;
        __syncthreads();
    }
    if (idx < N_NODES) {
        int excl = sm[threadIdx.x] - x + base;
        g_off[idx] = excl;
        g_pos[idx] = excl;
    }
}

// ---------------------------------------------------------------------------
// Counting-sort edges by dst (2 edges per thread):
// record = (src * ROW_U2, f32 val bits).
// ---------------------------------------------------------------------------
__global__ void scatter_kernel(const int* __restrict__ src,
                               const int* __restrict__ dst,
                               const float* __restrict__ val) {
    int e = blockIdx.x * blockDim.x + threadIdx.x;
    if (e < N_EDGES / 2) {
        int2   s = __ldg((const int2*)src + e);
        int2   d = __ldg((const int2*)dst + e);
        float2 v = __ldg((const float2*)val + e);
        int p0 = atomicAdd(&g_pos[d.x], 1);
        g_edges[p0] = make_int2(s.x * ROW_U2, __float_as_int(v.x));
        int p1 = atomicAdd(&g_pos[d.y], 1);
        g_edges[p1] = make_int2(s.y * ROW_U2, __float_as_int(v.y));
    }
}

// ---------------------------------------------------------------------------
// CSR SpMM, pair scheme (proven across 4 benches: 32 regs, 84% occ,
// 77.2-77.9us/layer): one warp per destination node; lanes 0-15 process
// even edges, lanes 16-31 odd edges; each lane owns 4 dims (uint2 = 2
// half2). Per inner iteration 2 edges: 1 LDS.64 + 1 LDG.64 + 4 cvt +
// 4 FFMA / lane. f32 accumulation, cross-half combine via SHFL.XOR(16).
// FINAL fuses out = (b0+b1+b2+h3)*0.25 and restores g_cnt == 0.
// ---------------------------------------------------------------------------
template<bool FINAL>
__global__ __launch_bounds__(256)
void spmm_csr_kernel(const __half2* __restrict__ hin,
                     __half2* __restrict__ hout,
                     float* __restrict__ out) {
    __shared__ int2 sm_ed[8][32];
    int wl   = threadIdx.x >> 5;
    int node = blockIdx.x * (blockDim.x >> 5) + wl;
    int lane = threadIdx.x & 31;
    if (node >= N_NODES) return;

    int start = g_off[node];
    int n     = g_cnt[node];
    int half  = lane >> 4;       // which edge of the pair this lane serves
    int hoff  = lane & 15;       // which uint2 (4 dims) of the row

    const uint2* __restrict__ hp = (const uint2*)hin;

    float s0 = 0.f, s1 = 0.f, s2 = 0.f, s3 = 0.f;
    int i = 0;
    for (; i + 32 <= n; i += 32) {
        sm_ed[wl][lane] = __ldg(&g_edges[start + i + lane]);
        __syncwarp();
        #pragma unroll
        for (int j = 0; j < 16; j++) {
            int2 e  = sm_ed[wl][2 * j + half];
            float v = __int_as_float(e.y);
            uint2 x = __ldg(&hp[e.x + hoff]);
            float2 fa = __half22float2(*(const __half2*)&x.x);
            float2 fb = __half22float2(*(const __half2*)&x.y);
            s0 += v * fa.x; s1 += v * fa.y;
            s2 += v * fb.x; s3 += v * fb.y;
        }
        __syncwarp();
    }
    int rem = n - i;
    if (rem > 0) {
        int2 ed = make_int2(0, 0);                      // zero-pad (v=0)
        if (lane < rem) ed = __ldg(&g_edges[start + i + lane]);
        sm_ed[wl][lane] = ed;
        __syncwarp();
        int npair = (rem + 1) >> 1;
        for (int j = 0; j < npair; j++) {
            int2 e  = sm_ed[wl][2 * j + half];
            float v = __int_as_float(e.y);
            uint2 x = __ldg(&hp[e.x + hoff]);
            float2 fa = __half22float2(*(const __half2*)&x.x);
            float2 fb = __half22float2(*(const __half2*)&x.y);
            s0 += v * fa.x; s1 += v * fa.y;
            s2 += v * fb.x; s3 += v * fb.y;
        }
    }

    // combine the two half-warps (even-edge sums + odd-edge sums)
    s0 += __shfl_xor_sync(0xffffffffu, s0, 16);
    s1 += __shfl_xor_sync(0xffffffffu, s1, 16);
    s2 += __shfl_xor_sync(0xffffffffu, s2, 16);
    s3 += __shfl_xor_sync(0xffffffffu, s3, 16);

    if (lane < 16) {
        size_t o = (size_t)node * ROW_U2 + hoff;        // uint2 / float4 index
        if (!FINAL) {
            __half2 ha = __floats2half2_rn(s0, s1);
            __half2 hb = __floats2half2_rn(s2, s3);
            uint2 r;
            r.x = *(const unsigned int*)&ha;
            r.y = *(const unsigned int*)&hb;
            ((uint2*)hout)[o] = r;
        } else {
            uint2 p0 = ((const uint2*)g_b0)[o];
            uint2 p1 = ((const uint2*)g_b1)[o];
            uint2 p2 = ((const uint2*)hin)[o];          // hin == g_b2 here
            float2 a0 = __half22float2(*(const __half2*)&p0.x);
            float2 b0_ = __half22float2(*(const __half2*)&p0.y);
            float2 a1 = __half22float2(*(const __half2*)&p1.x);
            float2 b1_ = __half22float2(*(const __half2*)&p1.y);
            float2 a2 = __half22float2(*(const __half2*)&p2.x);
            float2 b2_ = __half22float2(*(const __half2*)&p2.y);
            float4 r;
            r.x = (a0.x + a1.x + a2.x + s0) * 0.25f;
            r.y = (a0.y + a1.y + a2.y + s1) * 0.25f;
            r.z = (b0_.x + b1_.x + b2_.x + s2) * 0.25f;
            r.w = (b0_.y + b1_.y + b2_.y + s3) * 0.25f;
            ((float4*)out)[o] = r;
        }
    }
    if (FINAL && lane == 0) g_cnt[node] = 0;            // restore invariant
}

// ---------------------------------------------------------------------------
extern "C" void kernel_launch(void* const* d_in, const int* in_sizes, int n_in,
                              void* d_out, int out_size) {
    const float* user_emb = (const float*)d_in[0];
    const float* item_emb = (const float*)d_in[1];
    const int*   edge_src = (const int*)d_in[2];
    const int*   edge_dst = (const int*)d_in[3];
    const float* edge_val = (const float*)d_in[4];
    float* out = (float*)d_out;

    __half2 *b0, *b1, *b2;
    cudaGetSymbolAddress((void**)&b0, g_b0);
    cudaGetSymbolAddress((void**)&b1, g_b1);
    cudaGetSymbolAddress((void**)&b2, g_b2);

    const int TB = 256;
    const int grid_init  = (int)((N_H2 + TB - 1) / TB);            // covers 3M edge-pairs too
    const int grid_edge2 = (N_EDGES / 2 + TB - 1) / TB;
    const int grid_spmm  = (N_NODES * 32 + TB - 1) / TB;           // 1 warp / node

    // 0: fused init + dst histogram (g_cnt is 0 on entry by invariant)
    init_hist_kernel<<<grid_init, TB>>>(user_emb, item_emb, edge_dst);
    // 1: exclusive scan -> g_off, g_pos
    scan_kernel<<<NB_SCAN, SCAN_B>>>();
    // 2: counting-sort edges by dst (int2 records, f32 weights)
    scatter_kernel<<<grid_edge2, TB>>>(edge_src, edge_dst, edge_val);

    // 3: Layer 1: b0 -> b1
    spmm_csr_kernel<false><<<grid_spmm, TB>>>(b0, b1, nullptr);
    // 4: Layer 2: b1 -> b2
    spmm_csr_kernel<false><<<grid_spmm, TB>>>(b1, b2, nullptr);
    // 5: Layer 3: b2 -> (h3 on the fly), out = (b0+b1+b2+h3) * 0.25, reset g_cnt
    spmm_csr_kernel<true><<<grid_spmm, TB>>>(b2, nullptr, out);
}